// round 16
// baseline (speedup 1.0000x reference)
#include <cuda_runtime.h>
#include <cuda_fp16.h>
#include <cstdint>

// ---------------------------------------------------------------------------
// Problem constants
// ---------------------------------------------------------------------------
namespace {
constexpr int kB = 16;
constexpr int kT = 2048;
constexpr int kC = 1024;
constexpr int kH = 64;
constexpr int kRows = kB * kT;     // 32768
constexpr int kQT = kT / 64;       // 32 q-tiles per batch

// QKV GEMM smem (bytes): fragment-major, K-chunk 64, double buffer (R15)
constexpr int G_AH = 0;            // 16 A-frags x 512B (X single)
constexpr int G_BH = 8192;         // 96 B-frags x 256B (W single)
constexpr int G_BUF = 32768;
constexpr int QKV_SMEM = 2 * G_BUF;          // 65536 -> 2 CTAs/SM

// Attention smem (bytes): BN=128
constexpr int BK_KH = 0;           // K: 16KB
constexpr int BK_VH = 16384;       // V: 16KB
constexpr int ABUFSZ = 32768;
constexpr int ATTN_SMEM = 2 * ABUFSZ;        // 65536
}

// Scratch (__device__ globals: allocation-free)
__device__ __half g_Qh[kRows * kH];                 // Q single fp16 (pre-scaled)
__device__ __half g_KFh[kRows * kH];                // K single, fragment-major
__device__ __half g_VFh[kB * kH * kT];              // V^T single, fragment-major
__device__ __half g_WFh[192 * 1024];                // W single, fragment-major
// Split-KV partials: 16 batches x 16 heavy tiles x 2 parts
__device__ float g_pO[kB * 16 * 2 * 64 * 64];       // unnormalized O
__device__ float g_pM[kB * 16 * 2 * 64];            // running max (log2 domain)
__device__ float g_pL[kB * 16 * 2 * 64];            // running sum

// ---------------------------------------------------------------------------
// PTX helpers (baseline sm_80+ — survive compute_103 lowering)
// ---------------------------------------------------------------------------
__device__ __forceinline__ void mma16816(float* d, const uint32_t* a,
                                         const uint32_t* b) {
    asm volatile(
        "mma.sync.aligned.m16n8k16.row.col.f32.f16.f16.f32 "
        "{%0,%1,%2,%3}, {%4,%5,%6,%7}, {%8,%9}, {%0,%1,%2,%3};"
        : "+f"(d[0]), "+f"(d[1]), "+f"(d[2]), "+f"(d[3])
        : "r"(a[0]), "r"(a[1]), "r"(a[2]), "r"(a[3]), "r"(b[0]), "r"(b[1]));
}
__device__ __forceinline__ uint32_t f2pack(float lo, float hi) {
    uint32_t r;
    asm("cvt.rn.f16x2.f32 %0, %1, %2;" : "=r"(r) : "f"(hi), "f"(lo));
    return r;
}
__device__ __forceinline__ uint32_t smem_addr(const void* p) {
    return (uint32_t)__cvta_generic_to_shared(p);
}
#define CP_ASYNC16(dst, src) \
    asm volatile("cp.async.cg.shared.global [%0], [%1], 16;" \
                 :: "r"(dst), "l"(src))
#define CP_COMMIT() asm volatile("cp.async.commit_group;" ::: "memory")
#define CP_WAIT0()  asm volatile("cp.async.wait_group 0;" ::: "memory")
#define CP_WAIT1()  asm volatile("cp.async.wait_group 1;" ::: "memory")

// Fragment-major u32-word index for attention K (B-operand view)
__device__ __forceinline__ int bfrag_idx(int batch, int tok, int h) {
    const int jt = tok >> 6, nf = (tok >> 3) & 7, r = tok & 7;
    const int ks = h >> 4, sel = (h >> 3) & 1, q2 = (h >> 1) & 3;
    return (((batch * 32 + jt) * 32) + nf * 4 + ks) * 64 + (r * 4 + q2) * 2 + sel;
}

// ---------------------------------------------------------------------------
// Prep: W -> fragment-major single fp16.
// ---------------------------------------------------------------------------
__global__ void wprep_kernel(const float* __restrict__ Wq,
                             const float* __restrict__ Wk,
                             const float* __restrict__ Wv) {
    const int idx = blockIdx.x * 256 + threadIdx.x;   // < 98304
    const int frag = idx >> 6, ww = idx & 63;
    const int r = ww >> 3, q2 = (ww >> 1) & 3, sel = ww & 1;
    const int ks_g = frag / 24, nb = frag % 24;
    const int n = nb * 8 + r;
    const int k = ks_g * 16 + sel * 8 + q2 * 2;
    const int mat = n >> 6, col = n & 63;
    const float* W = (mat == 0) ? Wq : (mat == 1) ? Wk : Wv;
    const float v0 = W[k * 64 + col];
    const float v1 = W[(k + 1) * 64 + col];
    reinterpret_cast<uint32_t*>(g_WFh)[idx] = f2pack(v0, v1);
}

// ---------------------------------------------------------------------------
// QKV GEMM (R15-validated): fp16 HMMA, X single x W single, CTA 64x192,
// 256 threads, occ 2, fragment-major smem, fused V^T scatter.
// ---------------------------------------------------------------------------
__global__ __launch_bounds__(256, 2)
void qkv_mma_kernel(const float* __restrict__ x,
                    const float* __restrict__ bq,
                    const float* __restrict__ bk,
                    const float* __restrict__ bv) {
    extern __shared__ __align__(16) char sm[];
    const int tid  = threadIdx.x;
    const int lane = tid & 31;
    const int w    = tid >> 5;
    const int m0   = (w >> 2) * 32;
    const int n0   = (w & 3) * 48;
    const int mb0  = (w >> 2) * 2;
    const int nb0  = (w & 3) * 6;
    const int r1   = lane >> 2;
    const int kq   = lane & 3;
    const int row0 = blockIdx.x * 64;

    float acc[2][6][4];
#pragma unroll
    for (int mf = 0; mf < 2; ++mf)
#pragma unroll
        for (int nf = 0; nf < 6; ++nf)
#pragma unroll
            for (int i = 0; i < 4; ++i) acc[mf][nf][i] = 0.f;

    float4 xr[4];

    auto ldg_x = [&](int k0) {
#pragma unroll
        for (int it = 0; it < 4; ++it) {
            const int e4 = tid + it * 256;
            const int m = e4 >> 4, k4 = (e4 & 15) * 4;
            xr[it] = *reinterpret_cast<const float4*>(
                &x[(size_t)(row0 + m) * kC + k0 + k4]);
        }
    };
    auto cp_w = [&](int ch, char* buf) {
        const char* wh = (const char*)g_WFh + (size_t)ch * 24576;
#pragma unroll
        for (int it = 0; it < 6; ++it) {
            const int off = (tid + it * 256) * 16;
            CP_ASYNC16(smem_addr(buf + G_BH + off), wh + off);
        }
    };
    auto sts_x = [&](char* buf) {
        uint32_t* A = reinterpret_cast<uint32_t*>(buf + G_AH);
#pragma unroll
        for (int it = 0; it < 4; ++it) {
            const int e4 = tid + it * 256;
            const int m = e4 >> 4, k4 = (e4 & 15) * 4;
            const float4 v = xr[it];
            const int mb = m >> 4;
            const int ks = k4 >> 4;
            const int j  = ((k4 >> 3) & 1) * 2 + ((m >> 3) & 1);
            const int l0 = (m & 7) * 4 + ((k4 >> 1) & 3);
            const int base = (mb * 4 + ks) * 128 + j;
            A[base + l0 * 4]       = f2pack(v.x, v.y);
            A[base + (l0 + 1) * 4] = f2pack(v.z, v.w);
        }
    };

    ldg_x(0);
    cp_w(0, sm);
    CP_COMMIT();
    sts_x(sm);
    CP_WAIT0();
    __syncthreads();

    for (int ch = 0; ch < 16; ++ch) {
        char* buf = sm + (ch & 1) * G_BUF;
        if (ch + 1 < 16) {
            ldg_x((ch + 1) * 64);
            cp_w(ch + 1, sm + ((ch + 1) & 1) * G_BUF);
        }
        CP_COMMIT();

        const char* Ab = buf + G_AH + mb0 * 2048 + lane * 16;
        const char* Bh = buf + G_BH + nb0 * 256 + lane * 8;

#pragma unroll
        for (int ks = 0; ks < 4; ++ks) {
            uint4 ah4[2];
#pragma unroll
            for (int mf = 0; mf < 2; ++mf) {
                const int aoff = (mf * 4 + ks) * 512;
                ah4[mf] = *reinterpret_cast<const uint4*>(Ab + aoff);
            }
#pragma unroll
            for (int nf = 0; nf < 6; ++nf) {
                const int boff = (ks * 24 + nf) * 256;
                uint2 bh = *reinterpret_cast<const uint2*>(Bh + boff);
#pragma unroll
                for (int mf = 0; mf < 2; ++mf) {
                    mma16816(acc[mf][nf], reinterpret_cast<uint32_t*>(&ah4[mf]),
                             reinterpret_cast<uint32_t*>(&bh));
                }
            }
        }

        if (ch + 1 < 16) {
            __syncthreads();
            sts_x(sm + ((ch + 1) & 1) * G_BUF);
            CP_WAIT0();
            __syncthreads();
        }
    }

    // ---- epilogue ----
    uint32_t* KFh = reinterpret_cast<uint32_t*>(g_KFh);
    auto vstore = [&](int rga, int hh, float val) {
        const int batch = rga >> 11;
        const int jt = (rga >> 6) & 31;
        const int t = rga & 63;
        const int ks = t >> 4, sel = (t >> 3) & 1;
        const int lane2 = (hh & 7) * 4 + ((t >> 1) & 3);
        const int widx = (((batch * 32 + jt) * 32) + (hh >> 3) * 4 + ks) * 64
                         + lane2 * 2 + sel;
        g_VFh[widx * 2 + (t & 1)] = __float2half(val);
    };
#pragma unroll
    for (int mf = 0; mf < 2; ++mf) {
        const int rg = row0 + m0 + mf * 16 + r1;
#pragma unroll
        for (int nf = 0; nf < 6; ++nf) {
            const int col = n0 + nf * 8 + kq * 2;
            const int mat = col >> 6, h = col & 63;
            const float* bias = (mat == 0) ? bq : (mat == 1) ? bk : bv;
            const float b0 = bias[h], b1 = bias[h + 1];
            const float v00 = acc[mf][nf][0] + b0;
            const float v01 = acc[mf][nf][1] + b1;
            const float v10 = acc[mf][nf][2] + b0;
            const float v11 = acc[mf][nf][3] + b1;
            if (mat == 2) {
                vstore(rg, h, v00);
                vstore(rg, h + 1, v01);
                vstore(rg + 8, h, v10);
                vstore(rg + 8, h + 1, v11);
            } else if (mat == 1) {
                const int batch = rg >> 11, tok = rg & 2047;
                KFh[bfrag_idx(batch, tok, h)]     = f2pack(v00, v01);
                KFh[bfrag_idx(batch, tok + 8, h)] = f2pack(v10, v11);
            } else {
                const float scl = 0.125f * 1.44269504f;
                *reinterpret_cast<uint32_t*>(g_Qh + (size_t)rg * kH + h) =
                    f2pack(v00 * scl, v01 * scl);
                *reinterpret_cast<uint32_t*>(g_Qh + (size_t)(rg + 8) * kH + h) =
                    f2pack(v10 * scl, v11 * scl);
            }
        }
    }
}

// ---------------------------------------------------------------------------
// Causal flash attention with SPLIT-KV for heavy q-tiles.
// Work item i = blockIdx.x >> 4 (i-major heavy-first), b = blockIdx.x & 15.
//   i in [0,32): split item — qt = 31 - (i>>1), part = i&1 (half j-range each),
//                 writes partial (O, m, l) to scratch.
//   i in [32,48): single item — qt = 47 - i, direct normalize+store.
// Body identical to R14/R15 kernel; only loop bounds + epilogue differ.
// ---------------------------------------------------------------------------
__global__ __launch_bounds__(128, 3)
void attn_mma_kernel(float* __restrict__ out) {
    extern __shared__ __align__(16) char sma[];

    const int tid  = threadIdx.x;
    const int lane = tid & 31;
    const int w    = tid >> 5;
    const int b    = blockIdx.x & 15;
    const int i    = blockIdx.x >> 4;      // 0..47, heavy-first

    int qt, part;
    bool split;
    if (i < 32) { qt = 31 - (i >> 1); part = i & 1; split = true; }
    else        { qt = 47 - i;        part = 0;     split = false; }
    const int q0 = qt * 64;
    const int njt2 = (qt >> 1) + 1;        // total 128-token iterations
    const int half = njt2 >> 1;
    const int it0 = (split && part == 1) ? half : 0;
    const int it1 = (split && part == 0) ? half : njt2;

    const int m0w  = w * 16;
    const int r1   = lane >> 2;
    const int kq   = lane & 3;

    uint32_t qhi[4][4];
    {
        const uint32_t* qh =
            reinterpret_cast<const uint32_t*>(g_Qh + ((size_t)b * kT + q0) * kH);
        const int rA = (m0w + r1) * 32, rB = rA + 8 * 32;
#pragma unroll
        for (int ks = 0; ks < 4; ++ks) {
            const int c0 = ks * 8 + kq;
            qhi[ks][0] = qh[rA + c0];
            qhi[ks][1] = qh[rB + c0];
            qhi[ks][2] = qh[rA + c0 + 4];
            qhi[ks][3] = qh[rB + c0 + 4];
        }
    }

    auto stage = [&](int it, char* buf) {
        const size_t base = ((size_t)b * 32 + it * 2) * 8192;
        const char* kh = (const char*)g_KFh + base;
        const char* vh = (const char*)g_VFh + base;
#pragma unroll
        for (int ii = 0; ii < 8; ++ii) {
            const int off = (tid + ii * 128) * 16;
            CP_ASYNC16(smem_addr(buf + BK_KH + off), kh + off);
            CP_ASYNC16(smem_addr(buf + BK_VH + off), vh + off);
        }
    };

    float o[8][4];
#pragma unroll
    for (int nf = 0; nf < 8; ++nf)
#pragma unroll
        for (int c = 0; c < 4; ++c) o[nf][c] = 0.f;
    float mrow[2] = {-1e30f, -1e30f};
    float lrow[2] = {0.f, 0.f};

    stage(it0, sma + (it0 & 1) * ABUFSZ);
    CP_COMMIT();

    for (int it = it0; it < it1; ++it) {
        if (it + 1 < it1) stage(it + 1, sma + ((it + 1) & 1) * ABUFSZ);
        CP_COMMIT();
        CP_WAIT1();
        __syncthreads();

        char* buf = sma + (it & 1) * ABUFSZ;
        const char* Kh = buf + BK_KH + lane * 8;
        const char* Vh = buf + BK_VH + lane * 8;

        // ---- S = Q K^T over 128 tokens ----
        float s[16][4];
#pragma unroll
        for (int nf = 0; nf < 16; ++nf)
#pragma unroll
            for (int c = 0; c < 4; ++c) s[nf][c] = 0.f;

#pragma unroll
        for (int ks = 0; ks < 4; ++ks) {
#pragma unroll
            for (int nf = 0; nf < 16; ++nf) {
                const int boff = (nf >> 3) * 8192 + (((nf & 7) * 4 + ks)) * 256;
                uint2 bh = *reinterpret_cast<const uint2*>(Kh + boff);
                mma16816(s[nf], qhi[ks], reinterpret_cast<uint32_t*>(&bh));
            }
        }

        // ---- causal mask (global last iteration only) + softmax (exp2) ----
        if (it == njt2 - 1) {
            const int qg1 = q0 + m0w + r1;
            const int qg2 = qg1 + 8;
#pragma unroll
            for (int nf = 0; nf < 16; ++nf) {
                const int kg0 = it * 128 + nf * 8 + kq * 2;
                s[nf][0] = (kg0     <= qg1) ? s[nf][0] : -1e30f;
                s[nf][1] = (kg0 + 1 <= qg1) ? s[nf][1] : -1e30f;
                s[nf][2] = (kg0     <= qg2) ? s[nf][2] : -1e30f;
                s[nf][3] = (kg0 + 1 <= qg2) ? s[nf][3] : -1e30f;
            }
        }
        float mx1 = -1e30f, mx2 = -1e30f;
#pragma unroll
        for (int nf = 0; nf < 16; ++nf) {
            mx1 = fmaxf(mx1, fmaxf(s[nf][0], s[nf][1]));
            mx2 = fmaxf(mx2, fmaxf(s[nf][2], s[nf][3]));
        }
        mx1 = fmaxf(mx1, __shfl_xor_sync(0xffffffffu, mx1, 1));
        mx1 = fmaxf(mx1, __shfl_xor_sync(0xffffffffu, mx1, 2));
        mx2 = fmaxf(mx2, __shfl_xor_sync(0xffffffffu, mx2, 1));
        mx2 = fmaxf(mx2, __shfl_xor_sync(0xffffffffu, mx2, 2));

        const float mn1 = fmaxf(mrow[0], mx1);
        const float mn2 = fmaxf(mrow[1], mx2);
        const float a1 = exp2f(mrow[0] - mn1);
        const float a2 = exp2f(mrow[1] - mn2);
        mrow[0] = mn1; mrow[1] = mn2;

        float rs1 = 0.f, rs2 = 0.f;
#pragma unroll
        for (int nf = 0; nf < 16; ++nf) {
            s[nf][0] = exp2f(s[nf][0] - mn1);
            s[nf][1] = exp2f(s[nf][1] - mn1);
            s[nf][2] = exp2f(s[nf][2] - mn2);
            s[nf][3] = exp2f(s[nf][3] - mn2);
            rs1 += s[nf][0] + s[nf][1];
            rs2 += s[nf][2] + s[nf][3];
        }
        rs1 += __shfl_xor_sync(0xffffffffu, rs1, 1);
        rs1 += __shfl_xor_sync(0xffffffffu, rs1, 2);
        rs2 += __shfl_xor_sync(0xffffffffu, rs2, 1);
        rs2 += __shfl_xor_sync(0xffffffffu, rs2, 2);
        lrow[0] = lrow[0] * a1 + rs1;
        lrow[1] = lrow[1] * a2 + rs2;
#pragma unroll
        for (int nf = 0; nf < 8; ++nf) {
            o[nf][0] *= a1; o[nf][1] *= a1;
            o[nf][2] *= a2; o[nf][3] *= a2;
        }

        // ---- O += P V over 128 tokens ----
#pragma unroll
        for (int ks = 0; ks < 8; ++ks) {
            uint32_t pah[4];
            const float* s0 = s[2 * ks];
            const float* s1 = s[2 * ks + 1];
            pah[0] = f2pack(s0[0], s0[1]);
            pah[1] = f2pack(s0[2], s0[3]);
            pah[2] = f2pack(s1[0], s1[1]);
            pah[3] = f2pack(s1[2], s1[3]);
#pragma unroll
            for (int nfh = 0; nfh < 8; ++nfh) {
                const int boff = (ks >> 2) * 8192 + (nfh * 4 + (ks & 3)) * 256;
                uint2 vh = *reinterpret_cast<const uint2*>(Vh + boff);
                mma16816(o[nfh], pah, reinterpret_cast<uint32_t*>(&vh));
            }
        }
        __syncthreads();
    }

    if (!split) {
        // ---- direct: normalize + store ----
        const float inv1 = 1.0f / lrow[0];
        const float inv2 = 1.0f / lrow[1];
        float* og = out + ((size_t)b * kT + q0 + m0w) * kH;
#pragma unroll
        for (int nf = 0; nf < 8; ++nf) {
            const int col = nf * 8 + kq * 2;
            float2 v0, v1;
            v0.x = o[nf][0] * inv1; v0.y = o[nf][1] * inv1;
            v1.x = o[nf][2] * inv2; v1.y = o[nf][3] * inv2;
            *reinterpret_cast<float2*>(&og[r1 * kH + col]) = v0;
            *reinterpret_cast<float2*>(&og[(r1 + 8) * kH + col]) = v1;
        }
    } else {
        // ---- partial: store unnormalized O + (m, l) per row ----
        const int hq = qt - 16;
        const int pbase = ((b * 16 + hq) * 2 + part);
        float* pO = g_pO + (size_t)pbase * 64 * 64;
        const int rowA = m0w + r1, rowB = rowA + 8;
#pragma unroll
        for (int nf = 0; nf < 8; ++nf) {
            const int col = nf * 8 + kq * 2;
            float2 v0, v1;
            v0.x = o[nf][0]; v0.y = o[nf][1];
            v1.x = o[nf][2]; v1.y = o[nf][3];
            *reinterpret_cast<float2*>(&pO[rowA * 64 + col]) = v0;
            *reinterpret_cast<float2*>(&pO[rowB * 64 + col]) = v1;
        }
        if (kq == 0) {
            g_pM[pbase * 64 + rowA] = mrow[0];
            g_pM[pbase * 64 + rowB] = mrow[1];
            g_pL[pbase * 64 + rowA] = lrow[0];
            g_pL[pbase * 64 + rowB] = lrow[1];
        }
    }
}

// ---------------------------------------------------------------------------
// Combine partials for heavy q-tiles. Grid = kB*16, block 256.
// Exact flash combination in fp32.
// ---------------------------------------------------------------------------
__global__ __launch_bounds__(256)
void combine_kernel(float* __restrict__ out) {
    const int b  = blockIdx.x >> 4;
    const int hq = blockIdx.x & 15;
    const int qt = hq + 16;
    const int q0 = qt * 64;
    const int row = threadIdx.x >> 2;       // 0..63
    const int cg  = threadIdx.x & 3;        // 16 cols each

    const int p0 = ((b * 16 + hq) * 2 + 0);
    const int p1 = p0 + 1;
    const float m1 = g_pM[p0 * 64 + row], l1 = g_pL[p0 * 64 + row];
    const float m2 = g_pM[p1 * 64 + row], l2 = g_pL[p1 * 64 + row];
    const float M  = fmaxf(m1, m2);
    const float w1 = exp2f(m1 - M), w2 = exp2f(m2 - M);
    const float inv = 1.0f / (l1 * w1 + l2 * w2);

    const float* o1 = g_pO + (size_t)p0 * 64 * 64 + row * 64;
    const float* o2 = g_pO + (size_t)p1 * 64 * 64 + row * 64;
    float* og = out + ((size_t)b * kT + q0 + row) * kH;
#pragma unroll
    for (int c = cg * 16; c < cg * 16 + 16; c += 4) {
        const float4 a = *reinterpret_cast<const float4*>(o1 + c);
        const float4 d = *reinterpret_cast<const float4*>(o2 + c);
        float4 r;
        r.x = (a.x * w1 + d.x * w2) * inv;
        r.y = (a.y * w1 + d.y * w2) * inv;
        r.z = (a.z * w1 + d.z * w2) * inv;
        r.w = (a.w * w1 + d.w * w2) * inv;
        *reinterpret_cast<float4*>(og + c) = r;
    }
}

// ---------------------------------------------------------------------------
extern "C" void kernel_launch(void* const* d_in, const int* in_sizes, int n_in,
                              void* d_out, int out_size) {
    (void)in_sizes; (void)n_in; (void)out_size;
    const float* x  = (const float*)d_in[0];
    const float* Wq = (const float*)d_in[1];
    const float* bq = (const float*)d_in[2];
    const float* Wk = (const float*)d_in[3];
    const float* bk = (const float*)d_in[4];
    const float* Wv = (const float*)d_in[5];
    const float* bv = (const float*)d_in[6];
    float* out = (float*)d_out;

    wprep_kernel<<<384, 256>>>(Wq, Wk, Wv);

    cudaFuncSetAttribute(qkv_mma_kernel, cudaFuncAttributeMaxDynamicSharedMemorySize,
                         QKV_SMEM);
    qkv_mma_kernel<<<kRows / 64, 256, QKV_SMEM>>>(x, bq, bk, bv);

    cudaFuncSetAttribute(attn_mma_kernel, cudaFuncAttributeMaxDynamicSharedMemorySize,
                         ATTN_SMEM);
    attn_mma_kernel<<<48 * kB, 128, ATTN_SMEM>>>(out);

    combine_kernel<<<kB * 16, 256>>>(out);
}